// round 2
// baseline (speedup 1.0000x reference)
#include <cuda_runtime.h>
#include <math.h>

#define NB   4
#define NC   256
#define NC2  512
#define NPIX 4096   // 64*64
#define SMPAD 132

// ---------------- scratch (no allocations allowed) ----------------
__device__ __align__(128) float g_q   [(size_t)NB*NC *NPIX];   // 16.8 MB
__device__ __align__(128) float g_kv  [(size_t)NB*NC2*NPIX];   // 33.6 MB
__device__ __align__(128) float g_attn[(size_t)NB*NPIX*NPIX];  // 268 MB
__device__ __align__(128) float g_o   [(size_t)NB*NC *NPIX];   // 16.8 MB
__device__ __align__(128) float g_fused[(size_t)NB*NC *NPIX];  // 16.8 MB
__device__ float g_gate[NB];

// ---------------- generic 128x128 SGEMM, 8x8 per thread, KT=16 ----------------
// C[m,n] = alpha * sum_k A(m,k)*B(k,n) (+ bias[m])
// AMODE 0: A(m,k)=A[m*lda+k]   AMODE 1: A(m,k)=A[k*lda+m]
// BMODE 0: B(k,n)=B[k*ldb+n]   BMODE 1: B(k,n)=B[n*ldb+k]
// Requires: M,N multiples of 128; K multiple of 16 (all shapes here qualify).
template<int AMODE, int BMODE, bool HAS_BIAS>
__global__ __launch_bounds__(256)
void gemm128(const float* __restrict__ A, const float* __restrict__ Bm,
             const float* __restrict__ bias, float* __restrict__ Cm,
             int K, int lda, int ldb, int ldc, float alpha,
             long long sA, long long sB, long long sC)
{
    A  += (long long)blockIdx.z * sA;
    Bm += (long long)blockIdx.z * sB;
    Cm += (long long)blockIdx.z * sC;

    __shared__ __align__(16) float As[16][SMPAD];
    __shared__ __align__(16) float Bs[16][SMPAD];

    const int m0 = blockIdx.y << 7;
    const int n0 = blockIdx.x << 7;
    const int tid = threadIdx.x;
    const int tx = tid & 15, ty = tid >> 4;

    float acc[8][8];
    #pragma unroll
    for (int i = 0; i < 8; i++)
        #pragma unroll
        for (int j = 0; j < 8; j++) acc[i][j] = 0.f;

    for (int k0 = 0; k0 < K; k0 += 16) {
        // ---- load A tile: As[kk][mm] = A(m0+mm, k0+kk)   (2048 elems, 8/thread)
        if (AMODE == 1) {
            #pragma unroll
            for (int r = 0; r < 8; r++) {
                int e = tid + (r << 8);
                int kk = e >> 7, mm = e & 127;
                As[kk][mm] = A[(long long)(k0 + kk) * lda + m0 + mm];
            }
        } else {
            // scalar transpose loads (alignment-safe for harness inputs)
            #pragma unroll
            for (int r = 0; r < 8; r++) {
                int e = tid + (r << 8);
                int kk = e & 15, mm = e >> 4;
                As[kk][mm] = A[(long long)(m0 + mm) * lda + k0 + kk];
            }
        }
        // ---- load B tile: Bs[kk][nn] = B(k0+kk, n0+nn)
        if (BMODE == 0) {
            #pragma unroll
            for (int r = 0; r < 8; r++) {
                int e = tid + (r << 8);
                int kk = e >> 7, nn = e & 127;
                Bs[kk][nn] = Bm[(long long)(k0 + kk) * ldb + n0 + nn];
            }
        } else {
            // B is internal scratch (g_attn): 16B-aligned, vector load ok
            int nn = tid >> 1, h = (tid & 1) << 3;
            #pragma unroll
            for (int q = 0; q < 2; q++) {
                float4 v = *(const float4*)(Bm + (long long)(n0 + nn) * ldb + k0 + h + 4 * q);
                Bs[h + 4*q + 0][nn] = v.x; Bs[h + 4*q + 1][nn] = v.y;
                Bs[h + 4*q + 2][nn] = v.z; Bs[h + 4*q + 3][nn] = v.w;
            }
        }
        __syncthreads();

        #pragma unroll
        for (int kk = 0; kk < 16; kk++) {
            float a[8], b[8];
            *(float4*)(a)     = *(const float4*)&As[kk][ty << 3];
            *(float4*)(a + 4) = *(const float4*)&As[kk][(ty << 3) + 4];
            *(float4*)(b)     = *(const float4*)&Bs[kk][tx << 3];
            *(float4*)(b + 4) = *(const float4*)&Bs[kk][(tx << 3) + 4];
            #pragma unroll
            for (int i = 0; i < 8; i++)
                #pragma unroll
                for (int j = 0; j < 8; j++)
                    acc[i][j] = fmaf(a[i], b[j], acc[i][j]);
        }
        __syncthreads();
    }

    #pragma unroll
    for (int i = 0; i < 8; i++) {
        int row = m0 + (ty << 3) + i;
        float bv = HAS_BIAS ? bias[row] : 0.f;
        float* cp = Cm + (long long)row * ldc + n0 + (tx << 3);
        #pragma unroll
        for (int j = 0; j < 8; j += 4) {
            float4 v;
            v.x = fmaf(alpha, acc[i][j + 0], bv);
            v.y = fmaf(alpha, acc[i][j + 1], bv);
            v.z = fmaf(alpha, acc[i][j + 2], bv);
            v.w = fmaf(alpha, acc[i][j + 3], bv);
            *(float4*)(cp + j) = v;
        }
    }
}

// ---------------- row softmax over 4096 cols, one block per row ----------------
__global__ __launch_bounds__(256)
void softmax_rows(float* __restrict__ S)
{
    float4* row = (float4*)(S + (long long)blockIdx.x * NPIX);
    const int tid = threadIdx.x;
    float4 v[4];
    #pragma unroll
    for (int i = 0; i < 4; i++) v[i] = row[tid + (i << 8)];

    float m = v[0].x;
    #pragma unroll
    for (int i = 0; i < 4; i++) {
        m = fmaxf(m, fmaxf(fmaxf(v[i].x, v[i].y), fmaxf(v[i].z, v[i].w)));
    }
    #pragma unroll
    for (int o = 16; o; o >>= 1) m = fmaxf(m, __shfl_xor_sync(0xffffffffu, m, o));
    __shared__ float sm[8], ss[8];
    if ((tid & 31) == 0) sm[tid >> 5] = m;
    __syncthreads();
    #pragma unroll
    for (int w = 0; w < 8; w++) m = fmaxf(m, sm[w]);

    float s = 0.f;
    #pragma unroll
    for (int i = 0; i < 4; i++) {
        v[i].x = __expf(v[i].x - m); s += v[i].x;
        v[i].y = __expf(v[i].y - m); s += v[i].y;
        v[i].z = __expf(v[i].z - m); s += v[i].z;
        v[i].w = __expf(v[i].w - m); s += v[i].w;
    }
    #pragma unroll
    for (int o = 16; o; o >>= 1) s += __shfl_xor_sync(0xffffffffu, s, o);
    if ((tid & 31) == 0) ss[tid >> 5] = s;
    __syncthreads();
    s = 0.f;
    #pragma unroll
    for (int w = 0; w < 8; w++) s += ss[w];

    float r = 1.f / s;
    #pragma unroll
    for (int i = 0; i < 4; i++) {
        v[i].x *= r; v[i].y *= r; v[i].z *= r; v[i].w *= r;
        row[tid + (i << 8)] = v[i];
    }
}

// ---------------- gate MLP: p=mean(x_self), relu(g1), sigmoid(g2) ----------------
__global__ __launch_bounds__(256)
void gate_kernel(const float* __restrict__ xs,
                 const float* __restrict__ g1w, const float* __restrict__ g1b,
                 const float* __restrict__ g2w, const float* __restrict__ g2b)
{
    const int b = blockIdx.x, tid = threadIdx.x;
    const int wid = tid >> 5, lane = tid & 31;
    __shared__ float p[NC];
    const float* x = xs + (long long)b * NC * NPIX;
    for (int c = wid; c < NC; c += 8) {
        const float* xc = x + (long long)c * NPIX;
        float s = 0.f;
        for (int i = lane; i < NPIX; i += 32) s += xc[i];
        #pragma unroll
        for (int o = 16; o; o >>= 1) s += __shfl_xor_sync(0xffffffffu, s, o);
        if (!lane) p[c] = s * (1.0f / NPIX);
    }
    __syncthreads();
    __shared__ float hbuf[64];
    if (tid < 64) {
        float s = g1b[tid];
        for (int c = 0; c < NC; c++) s = fmaf(g1w[tid * NC + c], p[c], s);
        hbuf[tid] = fmaxf(s, 0.f);
    }
    __syncthreads();
    if (tid == 0) {
        float s = g2b[0];
        #pragma unroll
        for (int o = 0; o < 64; o++) s = fmaf(g2w[o], hbuf[o], s);
        g_gate[b] = 1.f / (1.f + __expf(-s));
    }
}

// ---------------- dwconv3x3 + BN + SiLU + gate*attn_out -> fused ----------------
__global__ __launch_bounds__(256)
void fuse_kernel(const float* __restrict__ xs,
                 const float* __restrict__ dww, const float* __restrict__ dwb,
                 const float* __restrict__ bng, const float* __restrict__ bnb,
                 const float* __restrict__ bnm, const float* __restrict__ bnv)
{
    const int bc = blockIdx.x;
    const int b = bc >> 8, c = bc & 255;
    const int tid = threadIdx.x;
    __shared__ float t[66 * 66];
    const float* x = xs + (long long)bc * NPIX;
    for (int i = tid; i < 66 * 66; i += 256) {
        int h = i / 66 - 1, w = i % 66 - 1;
        t[i] = (h >= 0 && h < 64 && w >= 0 && w < 64) ? x[h * 64 + w] : 0.f;
    }
    float wt[9];
    #pragma unroll
    for (int k = 0; k < 9; k++) wt[k] = dww[c * 9 + k];
    float scale = bng[c] * rsqrtf(bnv[c] + 1e-5f);
    float shift = fmaf(dwb[c] - bnm[c], scale, bnb[c]);
    float gate = g_gate[b];
    float* fptr = g_fused + (long long)bc * NPIX;
    const float* optr = g_o + (long long)bc * NPIX;
    __syncthreads();
    for (int i = tid; i < NPIX; i += 256) {
        int h = i >> 6, w = i & 63;
        const float* tp = &t[h * 66 + w];   // top-left of 3x3 window
        float conv = tp[0]   * wt[0] + tp[1]   * wt[1] + tp[2]   * wt[2]
                   + tp[66]  * wt[3] + tp[67]  * wt[4] + tp[68]  * wt[5]
                   + tp[132] * wt[6] + tp[133] * wt[7] + tp[134] * wt[8];
        float y = fmaf(conv, scale, shift);
        float lf = y / (1.f + __expf(-y));          // y * sigmoid(y)
        fptr[i] = fmaf(gate, optr[i], lf);
    }
}

// ---------------- launch ----------------
extern "C" void kernel_launch(void* const* d_in, const int* in_sizes, int n_in,
                              void* d_out, int out_size)
{
    const float* x_self  = (const float*)d_in[0];
    const float* x_other = (const float*)d_in[1];
    const float* q_w  = (const float*)d_in[2];
    const float* q_b  = (const float*)d_in[3];
    const float* kv_w = (const float*)d_in[4];
    const float* kv_b = (const float*)d_in[5];
    const float* g1_w = (const float*)d_in[6];
    const float* g1_b = (const float*)d_in[7];
    const float* g2_w = (const float*)d_in[8];
    const float* g2_b = (const float*)d_in[9];
    const float* dw_w = (const float*)d_in[10];
    const float* dw_b = (const float*)d_in[11];
    const float* bn_g = (const float*)d_in[12];
    const float* bn_b = (const float*)d_in[13];
    const float* bn_m = (const float*)d_in[14];
    const float* bn_v = (const float*)d_in[15];
    const float* out_w = (const float*)d_in[16];
    const float* out_b = (const float*)d_in[17];
    float* out = (float*)d_out;

    float *qp, *kvp, *ap, *op, *fp;
    cudaGetSymbolAddress((void**)&qp,  g_q);
    cudaGetSymbolAddress((void**)&kvp, g_kv);
    cudaGetSymbolAddress((void**)&ap,  g_attn);
    cudaGetSymbolAddress((void**)&op,  g_o);
    cudaGetSymbolAddress((void**)&fp,  g_fused);

    const long long sX  = (long long)NC  * NPIX;
    const long long sKV = (long long)NC2 * NPIX;
    const long long sS  = (long long)NPIX * NPIX;

    // gate MLP (independent of GEMMs)
    gate_kernel<<<NB, 256>>>(x_self, g1_w, g1_b, g2_w, g2_b);

    // Q = q_w @ x_self + q_b              [256 x 4096]
    gemm128<0, 0, true><<<dim3(32, 2, NB), 256>>>(
        q_w, x_self, q_b, qp, 256, 256, NPIX, NPIX, 1.f, 0, sX, sX);

    // KV = kv_w @ x_other + kv_b          [512 x 4096]
    gemm128<0, 0, true><<<dim3(32, 4, NB), 256>>>(
        kv_w, x_other, kv_b, kvp, 256, 256, NPIX, NPIX, 1.f, 0, sX, sKV);

    // S[n,m] = (Q^T K)/16                 [4096 x 4096]
    gemm128<1, 0, false><<<dim3(32, 32, NB), 256>>>(
        qp, kvp, nullptr, ap, 256, NPIX, NPIX, NPIX, 0.0625f, sX, sKV, sS);

    // row softmax
    softmax_rows<<<NB * NPIX, 256>>>(ap);

    // O[c,n] = sum_m V[c,m] P[n,m]  = V @ P^T   [256 x 4096]
    gemm128<0, 1, false><<<dim3(32, 2, NB), 256>>>(
        kvp + sX, ap, nullptr, op, NPIX, NPIX, NPIX, NPIX, 1.f, sKV, sS, sX);

    // local_feat (dwconv+BN+SiLU) + gate * O -> fused
    fuse_kernel<<<NB * NC, 256>>>(x_self, dw_w, dw_b, bn_g, bn_b, bn_m, bn_v);

    // out = out_w @ fused + out_b
    gemm128<0, 0, true><<<dim3(32, 2, NB), 256>>>(
        out_w, fp, out_b, out, 256, 256, NPIX, NPIX, 1.f, 0, sX, sX);
}

// round 5
// speedup vs baseline: 3.5124x; 3.5124x over previous
#include <cuda_runtime.h>
#include <cuda_bf16.h>
#include <cstdint>
#include <math.h>

#define NB   4
#define NC   256
#define NPIX 4096

// ================= scratch (no allocations allowed) =================
__device__ __align__(128) __nv_bfloat16 g_xs_hi[(size_t)NB*NPIX*NC];
__device__ __align__(128) __nv_bfloat16 g_xs_lo[(size_t)NB*NPIX*NC];
__device__ __align__(128) __nv_bfloat16 g_xo_hi[(size_t)NB*NPIX*NC];
__device__ __align__(128) __nv_bfloat16 g_xo_lo[(size_t)NB*NPIX*NC];
__device__ __align__(128) __nv_bfloat16 g_qt_hi[(size_t)NB*NPIX*NC];   // Q^T [n][c]
__device__ __align__(128) __nv_bfloat16 g_qt_lo[(size_t)NB*NPIX*NC];
__device__ __align__(128) __nv_bfloat16 g_kt_hi[(size_t)NB*NPIX*NC];   // K^T [m][c]
__device__ __align__(128) __nv_bfloat16 g_kt_lo[(size_t)NB*NPIX*NC];
__device__ __align__(128) __nv_bfloat16 g_v_hi [(size_t)NB*NC*NPIX];   // V [c][m]
__device__ __align__(128) __nv_bfloat16 g_v_lo [(size_t)NB*NC*NPIX];
__device__ __align__(128) float         g_attn [(size_t)NB*NPIX*NPIX]; // S fp32
__device__ __align__(128) __nv_bfloat16 g_p_hi [(size_t)NB*NPIX*NPIX]; // P [n][m]
__device__ __align__(128) __nv_bfloat16 g_p_lo [(size_t)NB*NPIX*NPIX];
__device__ __align__(128) float         g_o    [(size_t)NB*NPIX*NC];   // O [n][c]
__device__ __align__(128) float         g_fused[(size_t)NB*NC*NPIX];   // fused [c][n]
__device__ __align__(128) __nv_bfloat16 g_ft_hi[(size_t)NB*NPIX*NC];   // fused^T [n][c]
__device__ __align__(128) __nv_bfloat16 g_ft_lo[(size_t)NB*NPIX*NC];
__device__ __align__(128) __nv_bfloat16 g_qw_hi[NC*NC],   g_qw_lo[NC*NC];
__device__ __align__(128) __nv_bfloat16 g_kvw_hi[2*NC*NC],g_kvw_lo[2*NC*NC];
__device__ __align__(128) __nv_bfloat16 g_ow_hi[NC*NC],   g_ow_lo[NC*NC];
__device__ float g_gate[NB];

// ================= helpers =================
__device__ __forceinline__ uint32_t smem_u32(const void* p) {
    uint32_t a;
    asm("{ .reg .u64 t; cvta.to.shared.u64 t, %1; cvt.u32.u64 %0, t; }" : "=r"(a) : "l"(p));
    return a;
}
__device__ __forceinline__ void ldm_x4(uint32_t* r, uint32_t addr) {
    asm volatile("ldmatrix.sync.aligned.m8n8.x4.shared.b16 {%0,%1,%2,%3}, [%4];"
        : "=r"(r[0]), "=r"(r[1]), "=r"(r[2]), "=r"(r[3]) : "r"(addr));
}
__device__ __forceinline__ void mma16816(float* d, const uint32_t* a, uint32_t b0, uint32_t b1) {
    asm volatile("mma.sync.aligned.m16n8k16.row.col.f32.bf16.bf16.f32 "
        "{%0,%1,%2,%3}, {%4,%5,%6,%7}, {%8,%9}, {%0,%1,%2,%3};"
        : "+f"(d[0]), "+f"(d[1]), "+f"(d[2]), "+f"(d[3])
        : "r"(a[0]), "r"(a[1]), "r"(a[2]), "r"(a[3]), "r"(b0), "r"(b1));
}
#define CP_ASYNC16(saddr, gptr) \
    asm volatile("cp.async.cg.shared.global [%0], [%1], 16;" :: "r"(saddr), "l"(gptr))
#define CP_COMMIT() asm volatile("cp.async.commit_group;" ::: "memory")
#define CP_WAIT0()  asm volatile("cp.async.wait_group 0;" ::: "memory")

// SW128 swizzle on byte offset within a 128B-row tile
__device__ __forceinline__ uint32_t swz(uint32_t o) { return o ^ ((o >> 3) & 0x70); }

// ================= mma.sync GEMM: D[m][n] = alpha*sum_k A[m][k]*B[n][k] + bias =================
// A,B bf16 hi/lo K-major (row stride = K). CTA tile 128x128, K-chunks of 64, double-buffered.
// BIAS_MODE: 0 none, 1 per-row (M), 2 per-col (N). OUT_BF16: emit hi/lo bf16.
#define TILE_B   16384            // 128 rows x 128 bytes
#define BUF_B    (4 * TILE_B)     // AH AL BH BL
#define SM_TOT   (2 * BUF_B)      // double buffer = 131072

// async-copy one 128x64 bf16 tile (SW128-swizzled) from gmem
__device__ __forceinline__ void cp_tile(uint32_t dst, const __nv_bfloat16* src,
                                        int K, int tid) {
    #pragma unroll
    for (int r = 0; r < 4; r++) {
        int idx = tid + (r << 8);
        int row = idx >> 3, cc = idx & 7;
        uint32_t off = swz(row * 128 + cc * 16);
        CP_ASYNC16(dst + off, src + (size_t)row * K + cc * 8);
    }
}

template<int BIAS_MODE, bool OUT_BF16>
__global__ __launch_bounds__(256, 1)
void mma_gemm(const __nv_bfloat16* __restrict__ Ah, const __nv_bfloat16* __restrict__ Al,
              const __nv_bfloat16* __restrict__ Bh, const __nv_bfloat16* __restrict__ Bl,
              const float* __restrict__ bias, float alpha,
              float* __restrict__ Cf, __nv_bfloat16* __restrict__ Ch, __nv_bfloat16* __restrict__ Cl,
              int K, int ldc, long long sA, long long sB, long long sC)
{
    extern __shared__ __align__(1024) char dsm[];
    const uint32_t sb = smem_u32(dsm);
    const int tid = threadIdx.x, wid = tid >> 5, lane = tid & 31;
    const int warp_m = wid & 3, warp_n = wid >> 2;

    const size_t m0 = (size_t)blockIdx.y << 7;
    const size_t n0 = (size_t)blockIdx.x << 7;
    const __nv_bfloat16* pah = Ah + (long long)blockIdx.z * sA + m0 * K;
    const __nv_bfloat16* pal = Al + (long long)blockIdx.z * sA + m0 * K;
    const __nv_bfloat16* pbh = Bh + (long long)blockIdx.z * sB + n0 * K;
    const __nv_bfloat16* pbl = Bl + (long long)blockIdx.z * sB + n0 * K;

    float acc[2][8][4];
    #pragma unroll
    for (int i = 0; i < 2; i++)
        #pragma unroll
        for (int j = 0; j < 8; j++)
            #pragma unroll
            for (int q = 0; q < 4; q++) acc[i][j][q] = 0.f;

    const int nch = K >> 6;
    // prologue: chunk 0 into buffer 0
    cp_tile(sb,              pah, K, tid);
    cp_tile(sb +   TILE_B,   pal, K, tid);
    cp_tile(sb + 2*TILE_B,   pbh, K, tid);
    cp_tile(sb + 3*TILE_B,   pbl, K, tid);
    CP_COMMIT();

    for (int ch = 0; ch < nch; ch++) {
        CP_WAIT0();
        __syncthreads();
        if (ch + 1 < nch) {
            const size_t k0 = (size_t)(ch + 1) << 6;
            const uint32_t nb = sb + ((ch + 1) & 1) * BUF_B;
            cp_tile(nb,              pah + k0, K, tid);
            cp_tile(nb +   TILE_B,   pal + k0, K, tid);
            cp_tile(nb + 2*TILE_B,   pbh + k0, K, tid);
            cp_tile(nb + 3*TILE_B,   pbl + k0, K, tid);
            CP_COMMIT();
        }
        const uint32_t cbAH = sb + (ch & 1) * BUF_B;
        const uint32_t cbAL = cbAH + TILE_B;
        const uint32_t cbBH = cbAH + 2 * TILE_B;
        const uint32_t cbBL = cbAH + 3 * TILE_B;

        #pragma unroll
        for (int ks = 0; ks < 4; ks++) {
            const uint32_t koff = ks * 32 + (lane >> 4) * 16;
            uint32_t a_hi[2][4], a_lo[2][4];
            #pragma unroll
            for (int im = 0; im < 2; im++) {
                uint32_t off = swz((warp_m * 32 + im * 16 + (lane & 15)) * 128 + koff);
                ldm_x4(a_hi[im], cbAH + off);
                ldm_x4(a_lo[im], cbAL + off);
            }
            #pragma unroll
            for (int in2 = 0; in2 < 4; in2++) {
                uint32_t off = swz((warp_n * 64 + in2 * 16 + (lane & 15)) * 128 + koff);
                uint32_t bh[4], bl[4];
                ldm_x4(bh, cbBH + off);
                ldm_x4(bl, cbBL + off);
                #pragma unroll
                for (int im = 0; im < 2; im++) {
                    #pragma unroll
                    for (int s = 0; s < 2; s++) {
                        float* d = acc[im][in2 * 2 + s];
                        mma16816(d, a_hi[im], bh[s], bh[s + 2]);
                        mma16816(d, a_hi[im], bl[s], bl[s + 2]);
                        mma16816(d, a_lo[im], bh[s], bh[s + 2]);
                    }
                }
            }
        }
        __syncthreads();
    }

    // ---------------- epilogue ----------------
    const long long cbase = (long long)blockIdx.z * sC;
    #pragma unroll
    for (int im = 0; im < 2; im++) {
        const int r0 = (int)m0 + warp_m * 32 + im * 16 + (lane >> 2);
        const int r1 = r0 + 8;
        float rb0 = 0.f, rb1 = 0.f;
        if (BIAS_MODE == 1) { rb0 = bias[r0]; rb1 = bias[r1]; }
        #pragma unroll
        for (int in = 0; in < 8; in++) {
            const int c = (int)n0 + warp_n * 64 + in * 8 + (lane & 3) * 2;
            float cb0 = rb0, cb1 = rb0, cb2 = rb1, cb3 = rb1;
            if (BIAS_MODE == 2) { cb0 = cb2 = bias[c]; cb1 = cb3 = bias[c + 1]; }
            float v0 = fmaf(alpha, acc[im][in][0], cb0);
            float v1 = fmaf(alpha, acc[im][in][1], cb1);
            float v2 = fmaf(alpha, acc[im][in][2], cb2);
            float v3 = fmaf(alpha, acc[im][in][3], cb3);
            if (OUT_BF16) {
                __nv_bfloat16 h0 = __float2bfloat16(v0), h1 = __float2bfloat16(v1);
                __nv_bfloat16 h2 = __float2bfloat16(v2), h3 = __float2bfloat16(v3);
                *reinterpret_cast<__nv_bfloat162*>(Ch + cbase + (size_t)r0 * ldc + c) =
                    __nv_bfloat162(h0, h1);
                *reinterpret_cast<__nv_bfloat162*>(Ch + cbase + (size_t)r1 * ldc + c) =
                    __nv_bfloat162(h2, h3);
                *reinterpret_cast<__nv_bfloat162*>(Cl + cbase + (size_t)r0 * ldc + c) =
                    __nv_bfloat162(__float2bfloat16(v0 - __bfloat162float(h0)),
                                   __float2bfloat16(v1 - __bfloat162float(h1)));
                *reinterpret_cast<__nv_bfloat162*>(Cl + cbase + (size_t)r1 * ldc + c) =
                    __nv_bfloat162(__float2bfloat16(v2 - __bfloat162float(h2)),
                                   __float2bfloat16(v3 - __bfloat162float(h3)));
            } else {
                *reinterpret_cast<float2*>(Cf + cbase + (size_t)r0 * ldc + c) = make_float2(v0, v1);
                *reinterpret_cast<float2*>(Cf + cbase + (size_t)r1 * ldc + c) = make_float2(v2, v3);
            }
        }
    }
}

// ================= transpose + split: src fp32 [R][C] -> dst hi/lo bf16 [C][R] =================
__global__ void tconv(const float* __restrict__ src, __nv_bfloat16* __restrict__ dh,
                      __nv_bfloat16* __restrict__ dl, int R, int C)
{
    src += (size_t)blockIdx.z * R * C;
    dh  += (size_t)blockIdx.z * R * C;
    dl  += (size_t)blockIdx.z * R * C;
    __shared__ float t[32][33];
    const int c0 = blockIdx.x * 32, r0 = blockIdx.y * 32;
    const int tx = threadIdx.x, ty = threadIdx.y;
    #pragma unroll
    for (int i = 0; i < 4; i++)
        t[ty + 8 * i][tx] = src[(size_t)(r0 + ty + 8 * i) * C + c0 + tx];
    __syncthreads();
    #pragma unroll
    for (int i = 0; i < 4; i++) {
        float v = t[tx][ty + 8 * i];
        size_t o = (size_t)(c0 + ty + 8 * i) * R + r0 + tx;
        __nv_bfloat16 h = __float2bfloat16(v);
        dh[o] = h;
        dl[o] = __float2bfloat16(v - __bfloat162float(h));
    }
}

// ================= flat split (weights) =================
__global__ void fsplit(const float* __restrict__ src, __nv_bfloat16* __restrict__ dh,
                       __nv_bfloat16* __restrict__ dl, int n)
{
    int i = blockIdx.x * 256 + threadIdx.x;
    if (i < n) {
        float v = src[i];
        __nv_bfloat16 h = __float2bfloat16(v);
        dh[i] = h;
        dl[i] = __float2bfloat16(v - __bfloat162float(h));
    }
}

// ================= softmax: fp32 S row -> P hi/lo bf16 =================
__global__ __launch_bounds__(256)
void softmax_rows()
{
    const size_t ro = (size_t)blockIdx.x * NPIX;
    const float4* row = (const float4*)(g_attn + ro);
    const int tid = threadIdx.x;
    float4 v[4];
    #pragma unroll
    for (int i = 0; i < 4; i++) v[i] = row[tid + (i << 8)];

    float m = v[0].x;
    #pragma unroll
    for (int i = 0; i < 4; i++)
        m = fmaxf(m, fmaxf(fmaxf(v[i].x, v[i].y), fmaxf(v[i].z, v[i].w)));
    #pragma unroll
    for (int o = 16; o; o >>= 1) m = fmaxf(m, __shfl_xor_sync(0xffffffffu, m, o));
    __shared__ float sm[8], ss[8];
    if ((tid & 31) == 0) sm[tid >> 5] = m;
    __syncthreads();
    #pragma unroll
    for (int w = 0; w < 8; w++) m = fmaxf(m, sm[w]);

    float s = 0.f;
    #pragma unroll
    for (int i = 0; i < 4; i++) {
        v[i].x = __expf(v[i].x - m); s += v[i].x;
        v[i].y = __expf(v[i].y - m); s += v[i].y;
        v[i].z = __expf(v[i].z - m); s += v[i].z;
        v[i].w = __expf(v[i].w - m); s += v[i].w;
    }
    #pragma unroll
    for (int o = 16; o; o >>= 1) s += __shfl_xor_sync(0xffffffffu, s, o);
    if ((tid & 31) == 0) ss[tid >> 5] = s;
    __syncthreads();
    s = 0.f;
    #pragma unroll
    for (int w = 0; w < 8; w++) s += ss[w];

    const float r = 1.f / s;
    __nv_bfloat16* ph = g_p_hi + ro;
    __nv_bfloat16* pl = g_p_lo + ro;
    #pragma unroll
    for (int i = 0; i < 4; i++) {
        float p0 = v[i].x * r, p1 = v[i].y * r, p2 = v[i].z * r, p3 = v[i].w * r;
        __nv_bfloat16 h0 = __float2bfloat16(p0), h1 = __float2bfloat16(p1);
        __nv_bfloat16 h2 = __float2bfloat16(p2), h3 = __float2bfloat16(p3);
        int c0 = 4 * tid + 1024 * i;
        *reinterpret_cast<__nv_bfloat162*>(ph + c0)     = __nv_bfloat162(h0, h1);
        *reinterpret_cast<__nv_bfloat162*>(ph + c0 + 2) = __nv_bfloat162(h2, h3);
        *reinterpret_cast<__nv_bfloat162*>(pl + c0) =
            __nv_bfloat162(__float2bfloat16(p0 - __bfloat162float(h0)),
                           __float2bfloat16(p1 - __bfloat162float(h1)));
        *reinterpret_cast<__nv_bfloat162*>(pl + c0 + 2) =
            __nv_bfloat162(__float2bfloat16(p2 - __bfloat162float(h2)),
                           __float2bfloat16(p3 - __bfloat162float(h3)));
    }
}

// ================= gate MLP =================
__global__ __launch_bounds__(256)
void gate_kernel(const float* __restrict__ xs,
                 const float* __restrict__ g1w, const float* __restrict__ g1b,
                 const float* __restrict__ g2w, const float* __restrict__ g2b)
{
    const int b = blockIdx.x, tid = threadIdx.x;
    const int wid = tid >> 5, lane = tid & 31;
    __shared__ float p[NC];
    const float* x = xs + (size_t)b * NC * NPIX;
    for (int c = wid; c < NC; c += 8) {
        const float* xc = x + (size_t)c * NPIX;
        float s = 0.f;
        for (int i = lane; i < NPIX; i += 32) s += xc[i];
        #pragma unroll
        for (int o = 16; o; o >>= 1) s += __shfl_xor_sync(0xffffffffu, s, o);
        if (!lane) p[c] = s * (1.0f / NPIX);
    }
    __syncthreads();
    __shared__ float hbuf[64];
    if (tid < 64) {
        float s = g1b[tid];
        for (int c = 0; c < NC; c++) s = fmaf(g1w[tid * NC + c], p[c], s);
        hbuf[tid] = fmaxf(s, 0.f);
    }
    __syncthreads();
    if (tid == 0) {
        float s = g2b[0];
        #pragma unroll
        for (int o = 0; o < 64; o++) s = fmaf(g2w[o], hbuf[o], s);
        g_gate[b] = 1.f / (1.f + __expf(-s));
    }
}

// ================= dwconv3x3 + BN + SiLU + gate*O -> fused [c][n] =================
__global__ __launch_bounds__(256)
void fuse_kernel(const float* __restrict__ xs,
                 const float* __restrict__ dww, const float* __restrict__ dwb,
                 const float* __restrict__ bng, const float* __restrict__ bnb,
                 const float* __restrict__ bnm, const float* __restrict__ bnv)
{
    const int bc = blockIdx.x;
    const int b = bc >> 8, c = bc & 255;
    const int tid = threadIdx.x;
    __shared__ float t[66 * 66];
    const float* x = xs + (size_t)bc * NPIX;
    for (int i = tid; i < 66 * 66; i += 256) {
        int h = i / 66 - 1, w = i % 66 - 1;
        t[i] = (h >= 0 && h < 64 && w >= 0 && w < 64) ? x[h * 64 + w] : 0.f;
    }
    float wt[9];
    #pragma unroll
    for (int k = 0; k < 9; k++) wt[k] = dww[c * 9 + k];
    float scale = bng[c] * rsqrtf(bnv[c] + 1e-5f);
    float shift = fmaf(dwb[c] - bnm[c], scale, bnb[c]);
    float gate = g_gate[b];
    float* fptr = g_fused + (size_t)bc * NPIX;
    const float* optr = g_o + (size_t)b * NPIX * NC;   // [n][c]
    __syncthreads();
    for (int i = tid; i < NPIX; i += 256) {
        int h = i >> 6, w = i & 63;
        const float* tp = &t[h * 66 + w];
        float conv = tp[0]   * wt[0] + tp[1]   * wt[1] + tp[2]   * wt[2]
                   + tp[66]  * wt[3] + tp[67]  * wt[4] + tp[68]  * wt[5]
                   + tp[132] * wt[6] + tp[133] * wt[7] + tp[134] * wt[8];
        float y = fmaf(conv, scale, shift);
        float lf = y / (1.f + __expf(-y));
        fptr[i] = fmaf(gate, optr[(size_t)i * NC + c], lf);
    }
}

// ================= launch =================
extern "C" void kernel_launch(void* const* d_in, const int* in_sizes, int n_in,
                              void* d_out, int out_size)
{
    const float* x_self  = (const float*)d_in[0];
    const float* x_other = (const float*)d_in[1];
    const float* q_w  = (const float*)d_in[2];
    const float* q_b  = (const float*)d_in[3];
    const float* kv_w = (const float*)d_in[4];
    const float* kv_b = (const float*)d_in[5];
    const float* g1_w = (const float*)d_in[6];
    const float* g1_b = (const float*)d_in[7];
    const float* g2_w = (const float*)d_in[8];
    const float* g2_b = (const float*)d_in[9];
    const float* dw_w = (const float*)d_in[10];
    const float* dw_b = (const float*)d_in[11];
    const float* bn_g = (const float*)d_in[12];
    const float* bn_b = (const float*)d_in[13];
    const float* bn_m = (const float*)d_in[14];
    const float* bn_v = (const float*)d_in[15];
    const float* out_w = (const float*)d_in[16];
    const float* out_b = (const float*)d_in[17];
    float* out = (float*)d_out;

    cudaFuncSetAttribute(mma_gemm<2, true>,  cudaFuncAttributeMaxDynamicSharedMemorySize, SM_TOT);
    cudaFuncSetAttribute(mma_gemm<1, true>,  cudaFuncAttributeMaxDynamicSharedMemorySize, SM_TOT);
    cudaFuncSetAttribute(mma_gemm<0, false>, cudaFuncAttributeMaxDynamicSharedMemorySize, SM_TOT);
    cudaFuncSetAttribute(mma_gemm<1, false>, cudaFuncAttributeMaxDynamicSharedMemorySize, SM_TOT);

    #define SYM(p, s) cudaGetSymbolAddress((void**)&p, s)
    __nv_bfloat16 *xsh, *xsl, *xoh, *xol, *qth, *qtl, *kth, *ktl, *vh, *vl;
    __nv_bfloat16 *ph, *pl, *fth, *ftl, *qwh, *qwl, *kvwh, *kvwl, *owh, *owl;
    float *sp, *op, *fp;
    SYM(xsh, g_xs_hi); SYM(xsl, g_xs_lo); SYM(xoh, g_xo_hi); SYM(xol, g_xo_lo);
    SYM(qth, g_qt_hi); SYM(qtl, g_qt_lo); SYM(kth, g_kt_hi); SYM(ktl, g_kt_lo);
    SYM(vh, g_v_hi);   SYM(vl, g_v_lo);   SYM(ph, g_p_hi);   SYM(pl, g_p_lo);
    SYM(fth, g_ft_hi); SYM(ftl, g_ft_lo); SYM(qwh, g_qw_hi); SYM(qwl, g_qw_lo);
    SYM(kvwh, g_kvw_hi); SYM(kvwl, g_kvw_lo); SYM(owh, g_ow_hi); SYM(owl, g_ow_lo);
    SYM(sp, g_attn);   SYM(op, g_o);      SYM(fp, g_fused);
    #undef SYM

    const long long sX = (long long)NPIX * NC;
    const long long sS = (long long)NPIX * NPIX;

    // weight splits + input transpose-splits
    fsplit<<<(NC * NC + 255) / 256, 256>>>(q_w, qwh, qwl, NC * NC);
    fsplit<<<(2 * NC * NC + 255) / 256, 256>>>(kv_w, kvwh, kvwl, 2 * NC * NC);
    fsplit<<<(NC * NC + 255) / 256, 256>>>(out_w, owh, owl, NC * NC);
    tconv<<<dim3(NPIX / 32, NC / 32, NB), dim3(32, 8)>>>(x_self,  xsh, xsl, NC, NPIX);
    tconv<<<dim3(NPIX / 32, NC / 32, NB), dim3(32, 8)>>>(x_other, xoh, xol, NC, NPIX);

    gate_kernel<<<NB, 256>>>(x_self, g1_w, g1_b, g2_w, g2_b);

    // Qt[n][o] = sum_c xs[n][c] qw[o][c] + q_b[o]   (bf16 out, col bias)
    mma_gemm<2, true><<<dim3(2, 32, NB), 256, SM_TOT>>>(
        xsh, xsl, qwh, qwl, q_b, 1.f, nullptr, qth, qtl, NC, NC, sX, 0, sX);
    // Kt[m][o] = sum_c xo[m][c] kvw[o][c] + kv_b[o]
    mma_gemm<2, true><<<dim3(2, 32, NB), 256, SM_TOT>>>(
        xoh, xol, kvwh, kvwl, kv_b, 1.f, nullptr, kth, ktl, NC, NC, sX, 0, sX);
    // V[c][n] = sum_k kvw[256+c][k] xo[n][k] + kv_b[256+c]   (row bias)
    mma_gemm<1, true><<<dim3(32, 2, NB), 256, SM_TOT>>>(
        kvwh + NC * NC, kvwl + NC * NC, xoh, xol, kv_b + NC, 1.f,
        nullptr, vh, vl, NC, NPIX, 0, sX, sX);
    // S[n][m] = (1/16) sum_c Qt[n][c] Kt[m][c]   (fp32 out)
    mma_gemm<0, false><<<dim3(32, 32, NB), 256, SM_TOT>>>(
        qth, qtl, kth, ktl, nullptr, 0.0625f, sp, nullptr, nullptr, NC, NPIX, sX, sX, sS);

    softmax_rows<<<NB * NPIX, 256>>>();

    // O[n][c] = sum_m P[n][m] V[c][m]   (fp32 out, ldc = 256)
    mma_gemm<0, false><<<dim3(2, 32, NB), 256, SM_TOT>>>(
        ph, pl, vh, vl, nullptr, 1.f, op, nullptr, nullptr, NPIX, NC, sS, sX, sX);

    fuse_kernel<<<NB * NC, 256>>>(x_self, dw_w, dw_b, bn_g, bn_b, bn_m, bn_v);
    tconv<<<dim3(NPIX / 32, NC / 32, NB), dim3(32, 8)>>>(fp, fth, ftl, NC, NPIX);

    // out[o][n] = sum_c ow[o][c] ft[n][c] + out_b[o]   (fp32, row bias)
    mma_gemm<1, false><<<dim3(32, 2, NB), 256, SM_TOT>>>(
        owh, owl, fth, ftl, out_b, 1.f, out, nullptr, nullptr, NC, NPIX, 0, sX, sX);
}